// round 12
// baseline (speedup 1.0000x reference)
#include <cuda_runtime.h>
#include <cuda_bf16.h>
#include <cstdint>

// ============================================================================
// Problem constants
// ============================================================================
#define NROWS   200000          // nodes
#define NOUT    200001          // nodes + sentinel
#define FDIM    256
#define L0DIM   256
#define L1DIM   128
#define TILE_M  64
#define NTILES  3126            // ceil(200001/64); 3126*64 = 200064

// ============================================================================
// Device scratch (no allocations allowed -> __device__ globals)
// ============================================================================
// B-fragment-ordered weights: frag tile (k16 x n8) = 256 B ([lane][2 regs of 4B])
__device__ __align__(16) unsigned char g_W0f[32 * 16 * 256];   // 131072 B
__device__ __align__(16) unsigned char g_W1f[16 * 16 * 256];   //  65536 B (read from L2)
__device__ float g_c0[L0DIM];          // feature[0] @ W0[:256] + b0
__device__ float g_scores[NTILES * TILE_M];   // masked exp(score)
__device__ float g_total[1];

// ============================================================================
// PTX helpers (baseline sm_80+ instructions only — NO tcgen05: the harness
// PTX stage targets compute_103 (no 'a'), which rejects arch-accel features)
// ============================================================================
__device__ __forceinline__ uint32_t smem_u32(const void* p) {
    uint32_t a;
    asm("{ .reg .u64 t; cvta.to.shared.u64 t, %1; cvt.u32.u64 %0, t; }"
        : "=r"(a) : "l"(p));
    return a;
}

#define LDMATRIX_X4(r0, r1, r2, r3, addr) \
    asm volatile("ldmatrix.sync.aligned.m8n8.x4.shared.b16 {%0,%1,%2,%3}, [%4];" \
        : "=r"(r0), "=r"(r1), "=r"(r2), "=r"(r3) : "r"(addr))

#define MMA16816(d, a, b) \
    asm volatile("mma.sync.aligned.m16n8k16.row.col.f32.bf16.bf16.f32 " \
        "{%0,%1,%2,%3}, {%4,%5,%6,%7}, {%8,%9}, {%0,%1,%2,%3};" \
        : "+f"((d)[0]), "+f"((d)[1]), "+f"((d)[2]), "+f"((d)[3]) \
        : "r"((a)[0]), "r"((a)[1]), "r"((a)[2]), "r"((a)[3]), \
          "r"((b)[0]), "r"((b)[1]))

// Group-local barrier: groups (warps 0-7 / 8-15) sync independently.
#define GSYNC(gid) \
    asm volatile("bar.sync %0, %1;" :: "r"((gid) + 1), "r"(256) : "memory")

__device__ __forceinline__ uint32_t pack_bf16(float x, float y) {
    __nv_bfloat162 h = __floats2bfloat162_rn(x, y);   // x -> low, y -> high
    return *reinterpret_cast<uint32_t*>(&h);
}

// ============================================================================
// Prep kernel: weight fragments (coalesced 8B writes) + c0 (warp-per-n) + zero
// ============================================================================
// Fragment layout for mma.sync m16n8k16 B operand (col-major B = W^T[n][k]):
//   lane = (n%8)*4 + (k%8)/2 ; reg = (k%16)/8 ; pair = k%2
// Thread (frag, lane) writes its 8 bytes: k values k0,k0+1 (reg0), k0+8,k0+9
// (reg1) with k0 = kb*16 + 2*(lane&3), n = nb*8 + (lane>>2).
__global__ void prep_all(const float* __restrict__ W0,
                         const float* __restrict__ W1,
                         const float* __restrict__ feat,
                         const float* __restrict__ b0) {
    int b = blockIdx.x;
    if (b >= 96) {
        // c0[n] = feature[0] . W0[:256, n] + b0[n]  — one warp per n
        int w = threadIdx.x >> 5, lane = threadIdx.x & 31;
        int n = (b - 96) * 8 + w;
        float s = 0.f;
        #pragma unroll
        for (int kk = 0; kk < 8; kk++) {
            int k = kk * 32 + lane;
            s = fmaf(feat[k], W0[(size_t)k * L0DIM + n], s);
        }
        #pragma unroll
        for (int o = 16; o; o >>= 1) s += __shfl_xor_sync(0xffffffffu, s, o);
        if (lane == 0) {
            g_c0[n] = s + b0[n];
            if (n == 0) g_total[0] = 0.f;
        }
        return;
    }
    int t = b * 256 + threadIdx.x;        // 0..24575
    int lane = t & 31;
    int frag = t >> 5;                    // 0..767
    if (frag < 512) {                     // W0f: frag = nb*16 + kb (nb 0..31)
        int nb = frag >> 4, kb = frag & 15;
        int n  = nb * 8 + (lane >> 2);
        int k0 = kb * 16 + (lane & 3) * 2;
        const float* base = W0 + (size_t)FDIM * L0DIM;   // neighbor half rows
        float v0 = base[(size_t)(k0)     * L0DIM + n];
        float v1 = base[(size_t)(k0 + 1) * L0DIM + n];
        float v2 = base[(size_t)(k0 + 8) * L0DIM + n];
        float v3 = base[(size_t)(k0 + 9) * L0DIM + n];
        *(uint2*)(g_W0f + frag * 256 + lane * 8) =
            make_uint2(pack_bf16(v0, v1), pack_bf16(v2, v3));
    } else {                              // W1f: f = nb*16 + kb (nb 0..15)
        int f = frag - 512;
        int nb = f >> 4, kb = f & 15;
        int n  = nb * 8 + (lane >> 2);
        int k0 = kb * 16 + (lane & 3) * 2;
        float v0 = W1[(size_t)(k0)     * L1DIM + n];
        float v1 = W1[(size_t)(k0 + 1) * L1DIM + n];
        float v2 = W1[(size_t)(k0 + 8) * L1DIM + n];
        float v3 = W1[(size_t)(k0 + 9) * L1DIM + n];
        *(uint2*)(g_W1f + f * 256 + lane * 8) =
            make_uint2(pack_bf16(v0, v1), pack_bf16(v2, v3));
    }
}

// ============================================================================
// Main fused kernel: 512 threads = 2 independent 8-warp groups, each running
// the full tile pipeline (load X -> GEMM0 -> relu -> GEMM1 -> relu -> score
// -> masked exp) on its own tile with its own XS buffer and named barrier.
// Cross-group interleaving hides DRAM/LDS latency; 4 warps/SMSP feed HMMA.
// ============================================================================
// SMEM layout (dynamic):
#define OFF_C0   0                         // 256 f32
#define OFF_B1   1024                      // 128 f32
#define OFF_WS   1536                      // 128 f32
#define OFF_ACC  2048                      // 1 f32 (persistent exp-sum)
#define OFF_RED  2176                      // 2 x 1 KB score-reduction buffers
#define OFF_XS0  4224                      // 32 KB group-0: X / H0 frags
#define OFF_XS1  (OFF_XS0 + 32768)         // 32 KB group-1
#define OFF_W0F  (OFF_XS1 + 32768)         // 128 KB W0 B-fragments
#define SMEM_TOTAL (OFF_W0F + 131072)      // 200832 B

__global__ __launch_bounds__(512, 1) void policy_main(
    const float* __restrict__ feat,
    const int*   __restrict__ adj,
    const float* __restrict__ b1,
    const float* __restrict__ wsc)
{
    extern __shared__ unsigned char smem[];
    const uint32_t sb = smem_u32(smem);
    const int tid   = threadIdx.x;
    const int gid   = tid >> 8;            // group 0/1
    const int gtid  = tid & 255;           // tid within group
    const int wid_g = gtid >> 5;           // warp within group 0..7
    const int lane  = tid & 31;

    float* s_c0  = (float*)(smem + OFF_C0);
    float* s_b1  = (float*)(smem + OFF_B1);
    float* s_ws  = (float*)(smem + OFF_WS);
    float* s_acc = (float*)(smem + OFF_ACC);
    float* s_red = (float*)(smem + OFF_RED + gid * 1024);

    unsigned char* xs_ptr = smem + OFF_XS0 + (gid << 15);
    const uint32_t XS = sb + OFF_XS0 + ((uint32_t)gid << 15);

    // ---- one-time: constants + W0 frags gmem -> SMEM (all 512 threads) ----
    if (tid < 256) s_c0[tid] = g_c0[tid];
    if (tid < 128) { s_b1[tid] = b1[tid]; s_ws[tid] = wsc[tid]; }
    if (tid == 0) s_acc[0] = 0.f;
    {
        const float4* s0 = (const float4*)g_W0f;
        float4* d0 = (float4*)(smem + OFF_W0F);
        for (int i = tid; i < 131072 / 16; i += 512) d0[i] = s0[i];
    }
    __syncthreads();

    const float4* feat4 = (const float4*)feat;

    for (int tile = blockIdx.x * 2 + gid; tile < NTILES; tile += gridDim.x * 2) {

        // ==== Load X tile: 64 rows x 256 fp32 -> bf16, XOR-swizzled rows ====
        // Unit-granular: thread handles whole 16-B swizzle units (2 contiguous
        // float4 loads -> 1 STS.128). 2048 units, 8 per thread.
        {
            float4 pf[16];
            #pragma unroll
            for (int i = 0; i < 8; i++) {
                int j = i * 256 + gtid;        // unit index 0..2047
                int r = j >> 5;                // 0..63
                int u = j & 31;                // unit within row
                int row_g = tile * TILE_M + r;
                float4 v0 = make_float4(0.f, 0.f, 0.f, 0.f);
                float4 v1 = v0;
                if (row_g != 0 && row_g < NROWS) {
                    const float4* p = feat4 + (size_t)row_g * 64 + u * 2;
                    v0 = __ldg(p);
                    v1 = __ldg(p + 1);
                }
                pf[2 * i]     = v0;
                pf[2 * i + 1] = v1;
            }
            #pragma unroll
            for (int i = 0; i < 8; i++) {
                int j = i * 256 + gtid;
                int r = j >> 5;
                int u = j & 31;
                float4 v0 = pf[2 * i], v1 = pf[2 * i + 1];
                uint4 pk;
                pk.x = pack_bf16(v0.x, v0.y);
                pk.y = pack_bf16(v0.z, v0.w);
                pk.z = pack_bf16(v1.x, v1.y);
                pk.w = pack_bf16(v1.z, v1.w);
                uint32_t addr = (uint32_t)(r * 512 + (u ^ (r & 7)) * 16);
                *(uint4*)(xs_ptr + addr) = pk;
            }
        }
        GSYNC(gid);

        // ==== GEMM0: D0[64,256] = X[64,256] @ W0f ; warp w -> n [w*32,..) ====
        float acc[4][4][4];
        #pragma unroll
        for (int mt = 0; mt < 4; mt++)
            #pragma unroll
            for (int nt = 0; nt < 4; nt++)
                #pragma unroll
                for (int q = 0; q < 4; q++) acc[mt][nt][q] = 0.f;

        const int r_off = (lane & 7) + ((lane >> 3) & 1) * 8;   // row within m16
        const int u_hi  = (lane >> 4) & 1;                      // +1 unit for k+8

        #pragma unroll
        for (int ks = 0; ks < 16; ks++) {
            uint32_t a[4][4];
            #pragma unroll
            for (int mt = 0; mt < 4; mt++) {
                int r = mt * 16 + r_off;
                int u = ks * 2 + u_hi;
                uint32_t addr = XS + (uint32_t)(r * 512 + (u ^ (r & 7)) * 16);
                LDMATRIX_X4(a[mt][0], a[mt][1], a[mt][2], a[mt][3], addr);
            }
            #pragma unroll
            for (int nt = 0; nt < 4; nt++) {
                int n0 = wid_g * 32 + nt * 8;
                uint2 bv = *(const uint2*)(smem + OFF_W0F
                              + (((n0 >> 3) * 16 + ks) * 256) + lane * 8);
                uint32_t b[2]; b[0] = bv.x; b[1] = bv.y;
                #pragma unroll
                for (int mt = 0; mt < 4; mt++)
                    MMA16816(acc[mt][nt], a[mt], b);
            }
        }
        GSYNC(gid);   // all group warps done reading XS

        // ==== Epilogue0: relu(acc + c0) -> bf16 A-fragments into XS ====
        // accum lane map == A-frag lane map; combine nt pair -> 16B (a0..a3)
        #pragma unroll
        for (int mt = 0; mt < 4; mt++) {
            #pragma unroll
            for (int ntp = 0; ntp < 2; ntp++) {
                int nt0 = ntp * 2, nt1 = nt0 + 1;
                int nA = wid_g * 32 + nt0 * 8 + (lane & 3) * 2;
                int nB = wid_g * 32 + nt1 * 8 + (lane & 3) * 2;
                float cA0 = s_c0[nA], cA1 = s_c0[nA + 1];
                float cB0 = s_c0[nB], cB1 = s_c0[nB + 1];
                uint32_t r0 = pack_bf16(fmaxf(acc[mt][nt0][0] + cA0, 0.f),
                                        fmaxf(acc[mt][nt0][1] + cA1, 0.f));
                uint32_t r1 = pack_bf16(fmaxf(acc[mt][nt0][2] + cA0, 0.f),
                                        fmaxf(acc[mt][nt0][3] + cA1, 0.f));
                uint32_t r2 = pack_bf16(fmaxf(acc[mt][nt1][0] + cB0, 0.f),
                                        fmaxf(acc[mt][nt1][1] + cB1, 0.f));
                uint32_t r3 = pack_bf16(fmaxf(acc[mt][nt1][2] + cB0, 0.f),
                                        fmaxf(acc[mt][nt1][3] + cB1, 0.f));
                int ks1 = wid_g * 2 + ntp;  // this n-range is k-range in GEMM1
                uint32_t off = (uint32_t)((mt * 16 + ks1) * 512 + lane * 16);
                *(uint4*)(xs_ptr + off) = make_uint4(r0, r1, r2, r3);
            }
        }
        GSYNC(gid);

        // ==== GEMM1: D1[64,128] = H0[64,256] @ W1f(global/L2) ; 2(m)x4(n) ====
        const int warp_m = wid_g >> 2;    // 0..1 -> m base warp_m*32
        const int warp_n = wid_g & 3;     // 0..3 -> n base warp_n*32
        float acc2[2][4][4];
        #pragma unroll
        for (int mt = 0; mt < 2; mt++)
            #pragma unroll
            for (int nt = 0; nt < 4; nt++)
                #pragma unroll
                for (int q = 0; q < 4; q++) acc2[mt][nt][q] = 0.f;

        #pragma unroll
        for (int ks = 0; ks < 16; ks++) {
            uint32_t a2[2][4];
            #pragma unroll
            for (int mt = 0; mt < 2; mt++) {
                int mtg = warp_m * 2 + mt;
                uint4 av = *(uint4*)(xs_ptr + (mtg * 16 + ks) * 512 + lane * 16);
                a2[mt][0] = av.x; a2[mt][1] = av.y; a2[mt][2] = av.z; a2[mt][3] = av.w;
            }
            #pragma unroll
            for (int nt = 0; nt < 4; nt++) {
                int n0 = warp_n * 32 + nt * 8;
                uint2 bv = __ldg((const uint2*)(g_W1f
                              + (((n0 >> 3) * 16 + ks) * 256) + lane * 8));
                uint32_t b[2]; b[0] = bv.x; b[1] = bv.y;
                #pragma unroll
                for (int mt = 0; mt < 2; mt++)
                    MMA16816(acc2[mt][nt], a2[mt], b);
            }
        }
        GSYNC(gid);   // done reading XS (H0 frags)

        // ==== Epilogue1: score_r = sum_n relu(d + b1[n]) * ws[n] ====
        // Every s_red slot [64 rows][4 warp_n] is written exactly once.
        #pragma unroll
        for (int mt = 0; mt < 2; mt++) {
            float p0 = 0.f, p1 = 0.f;      // rows l/4 and l/4+8 of this m16 tile
            #pragma unroll
            for (int nt = 0; nt < 4; nt++) {
                int n = warp_n * 32 + nt * 8 + (lane & 3) * 2;
                float bb0 = s_b1[n], bb1 = s_b1[n + 1];
                float w0 = s_ws[n],  w1 = s_ws[n + 1];
                p0 = fmaf(fmaxf(acc2[mt][nt][0] + bb0, 0.f), w0, p0);
                p0 = fmaf(fmaxf(acc2[mt][nt][1] + bb1, 0.f), w1, p0);
                p1 = fmaf(fmaxf(acc2[mt][nt][2] + bb0, 0.f), w0, p1);
                p1 = fmaf(fmaxf(acc2[mt][nt][3] + bb1, 0.f), w1, p1);
            }
            p0 += __shfl_xor_sync(0xffffffff, p0, 1);
            p0 += __shfl_xor_sync(0xffffffff, p0, 2);
            p1 += __shfl_xor_sync(0xffffffff, p1, 1);
            p1 += __shfl_xor_sync(0xffffffff, p1, 2);
            if ((lane & 3) == 0) {
                int r = warp_m * 32 + mt * 16 + (lane >> 2);
                s_red[r * 4 + warp_n] = p0;
                s_red[(r + 8) * 4 + warp_n] = p1;
            }
        }
        GSYNC(gid);

        // ==== Fused masked exp + store + CTA partial sum ====
        // No trailing barrier: s_red is in its own region and is rewritten
        // only after the reading warps pass 3 later GSYNCs of the next tile.
        if (gtid < 64) {      // warps 0-1 of the group (full warps)
            float s = s_red[gtid * 4] + s_red[gtid * 4 + 1]
                    + s_red[gtid * 4 + 2] + s_red[gtid * 4 + 3];
            int row_g = tile * TILE_M + gtid;
            float e = 0.f;
            if (row_g < NOUT) {
                bool m = (row_g < NROWS) ? (adj[row_g] != 0) : true;
                e = m ? expf(s) : 0.f;     // scores are O(0.01): shift-free exp
                g_scores[row_g] = e;
            }
            e += __shfl_xor_sync(0xffffffff, e, 1);
            e += __shfl_xor_sync(0xffffffff, e, 2);
            e += __shfl_xor_sync(0xffffffff, e, 4);
            e += __shfl_xor_sync(0xffffffff, e, 8);
            e += __shfl_xor_sync(0xffffffff, e, 16);
            if (lane == 0) atomicAdd(s_acc, e);
        }
    }

    __syncthreads();
    if (tid == 0) atomicAdd(&g_total[0], s_acc[0]);
}

// ============================================================================
// Final normalize: out[i] = e_i / sum(e)   (masked entries have e_i = 0)
// ============================================================================
__global__ void finalize(float* __restrict__ out) {
    int i = blockIdx.x * 256 + threadIdx.x;
    if (i < NOUT) out[i] = g_scores[i] / g_total[0];
}

// ============================================================================
// kernel_launch
// ============================================================================
extern "C" void kernel_launch(void* const* d_in, const int* in_sizes, int n_in,
                              void* d_out, int out_size) {
    const int*   adj  = (const int*)d_in[0];
    const float* feat = (const float*)d_in[1];
    const float* W0   = (const float*)d_in[2];
    const float* b0   = (const float*)d_in[3];
    const float* W1   = (const float*)d_in[4];
    const float* b1   = (const float*)d_in[5];
    const float* wsc  = (const float*)d_in[6];
    float* out = (float*)d_out;

    cudaFuncSetAttribute(policy_main,
                         cudaFuncAttributeMaxDynamicSharedMemorySize, SMEM_TOTAL);

    int sms = 148;
    cudaDeviceGetAttribute(&sms, cudaDevAttrMultiProcessorCount, 0);
    if (sms < 1) sms = 148;
    if (sms * 2 > NTILES) sms = (NTILES + 1) / 2;

    prep_all<<<128, 256>>>(W0, W1, feat, b0);
    policy_main<<<sms, 512, SMEM_TOTAL>>>(feat, adj, b1, wsc);
    finalize<<<(NOUT + 255) / 256, 256>>>(out);
}

// round 13
// speedup vs baseline: 1.0773x; 1.0773x over previous
#include <cuda_runtime.h>
#include <cuda_bf16.h>
#include <cstdint>

// ============================================================================
// Problem constants
// ============================================================================
#define NROWS   200000          // nodes
#define NOUT    200001          // nodes + sentinel
#define FDIM    256
#define L0DIM   256
#define L1DIM   128
#define TILE_M  64
#define NTILES  3126            // ceil(200001/64); 3126*64 = 200064

// ============================================================================
// Device scratch (no allocations allowed -> __device__ globals)
// ============================================================================
// B-fragment-ordered weights: frag tile (k16 x n8) = 256 B ([lane][2 regs of 4B])
__device__ __align__(16) unsigned char g_W0f[32 * 16 * 256];   // 131072 B
__device__ __align__(16) unsigned char g_W1f[16 * 16 * 256];   //  65536 B (read from L2)
__device__ float g_c0[L0DIM];          // feature[0] @ W0[:256] + b0
__device__ float g_scores[NTILES * TILE_M];   // masked exp(score)
__device__ float g_total[1];

// ============================================================================
// PTX helpers (baseline sm_80+ instructions only — NO tcgen05: the harness
// PTX stage targets compute_103 (no 'a'), which rejects arch-accel features)
// ============================================================================
__device__ __forceinline__ uint32_t smem_u32(const void* p) {
    uint32_t a;
    asm("{ .reg .u64 t; cvta.to.shared.u64 t, %1; cvt.u32.u64 %0, t; }"
        : "=r"(a) : "l"(p));
    return a;
}

#define LDMATRIX_X4(r0, r1, r2, r3, addr) \
    asm volatile("ldmatrix.sync.aligned.m8n8.x4.shared.b16 {%0,%1,%2,%3}, [%4];" \
        : "=r"(r0), "=r"(r1), "=r"(r2), "=r"(r3) : "r"(addr))

#define MMA16816(d, a, b) \
    asm volatile("mma.sync.aligned.m16n8k16.row.col.f32.bf16.bf16.f32 " \
        "{%0,%1,%2,%3}, {%4,%5,%6,%7}, {%8,%9}, {%0,%1,%2,%3};" \
        : "+f"((d)[0]), "+f"((d)[1]), "+f"((d)[2]), "+f"((d)[3]) \
        : "r"((a)[0]), "r"((a)[1]), "r"((a)[2]), "r"((a)[3]), \
          "r"((b)[0]), "r"((b)[1]))

// Group-local barrier: groups (warps 0-7 / 8-15) sync independently.
#define GSYNC(gid) \
    asm volatile("bar.sync %0, %1;" :: "r"((gid) + 1), "r"(256) : "memory")

__device__ __forceinline__ uint32_t pack_bf16(float x, float y) {
    __nv_bfloat162 h = __floats2bfloat162_rn(x, y);   // x -> low, y -> high
    return *reinterpret_cast<uint32_t*>(&h);
}

// ============================================================================
// Prep kernel: weight fragments (coalesced 8B writes) + c0 (warp-per-n) + zero
// ============================================================================
// Fragment layout for mma.sync m16n8k16 B operand (col-major B = W^T[n][k]):
//   lane = (n%8)*4 + (k%8)/2 ; reg = (k%16)/8 ; pair = k%2
// Thread (frag, lane) writes its 8 bytes: k values k0,k0+1 (reg0), k0+8,k0+9
// (reg1) with k0 = kb*16 + 2*(lane&3), n = nb*8 + (lane>>2).
__global__ void prep_all(const float* __restrict__ W0,
                         const float* __restrict__ W1,
                         const float* __restrict__ feat,
                         const float* __restrict__ b0) {
    int b = blockIdx.x;
    if (b >= 96) {
        // c0[n] = feature[0] . W0[:256, n] + b0[n]  — one warp per n
        int w = threadIdx.x >> 5, lane = threadIdx.x & 31;
        int n = (b - 96) * 8 + w;
        float s = 0.f;
        #pragma unroll
        for (int kk = 0; kk < 8; kk++) {
            int k = kk * 32 + lane;
            s = fmaf(feat[k], W0[(size_t)k * L0DIM + n], s);
        }
        #pragma unroll
        for (int o = 16; o; o >>= 1) s += __shfl_xor_sync(0xffffffffu, s, o);
        if (lane == 0) {
            g_c0[n] = s + b0[n];
            if (n == 0) g_total[0] = 0.f;
        }
        return;
    }
    int t = b * 256 + threadIdx.x;        // 0..24575
    int lane = t & 31;
    int frag = t >> 5;                    // 0..767
    if (frag < 512) {                     // W0f: frag = nb*16 + kb (nb 0..31)
        int nb = frag >> 4, kb = frag & 15;
        int n  = nb * 8 + (lane >> 2);
        int k0 = kb * 16 + (lane & 3) * 2;
        const float* base = W0 + (size_t)FDIM * L0DIM;   // neighbor half rows
        float v0 = base[(size_t)(k0)     * L0DIM + n];
        float v1 = base[(size_t)(k0 + 1) * L0DIM + n];
        float v2 = base[(size_t)(k0 + 8) * L0DIM + n];
        float v3 = base[(size_t)(k0 + 9) * L0DIM + n];
        *(uint2*)(g_W0f + frag * 256 + lane * 8) =
            make_uint2(pack_bf16(v0, v1), pack_bf16(v2, v3));
    } else {                              // W1f: f = nb*16 + kb (nb 0..15)
        int f = frag - 512;
        int nb = f >> 4, kb = f & 15;
        int n  = nb * 8 + (lane >> 2);
        int k0 = kb * 16 + (lane & 3) * 2;
        float v0 = W1[(size_t)(k0)     * L1DIM + n];
        float v1 = W1[(size_t)(k0 + 1) * L1DIM + n];
        float v2 = W1[(size_t)(k0 + 8) * L1DIM + n];
        float v3 = W1[(size_t)(k0 + 9) * L1DIM + n];
        *(uint2*)(g_W1f + f * 256 + lane * 8) =
            make_uint2(pack_bf16(v0, v1), pack_bf16(v2, v3));
    }
}

// ============================================================================
// Main fused kernel: 512 threads = 2 independent 8-warp groups, each running
// the full tile pipeline on its own tile/XS buffer with named barriers.
// A one-time stagger puts the groups in ANTI-PHASE so group A's DRAM X load
// overlaps group B's GEMMs (identical periods preserve the offset).
// ============================================================================
// SMEM layout (dynamic):
#define OFF_C0   0                         // 256 f32
#define OFF_B1   1024                      // 128 f32
#define OFF_WS   1536                      // 128 f32
#define OFF_ACC  2048                      // 1 f32 (persistent exp-sum)
#define OFF_FLAG 2064                      // 1 int (stagger handshake)
#define OFF_XS0  2176                      // 32 KB group-0: X / H0 frags / s_red
#define OFF_XS1  (OFF_XS0 + 32768)         // 32 KB group-1
#define OFF_W0F  (OFF_XS1 + 32768)         // 128 KB W0 B-fragments
#define SMEM_TOTAL (OFF_W0F + 131072)      // 198784 B

__global__ __launch_bounds__(512, 1) void policy_main(
    const float* __restrict__ feat,
    const int*   __restrict__ adj,
    const float* __restrict__ b1,
    const float* __restrict__ wsc)
{
    extern __shared__ unsigned char smem[];
    const uint32_t sb = smem_u32(smem);
    const int tid   = threadIdx.x;
    const int gid   = tid >> 8;            // group 0/1
    const int gtid  = tid & 255;           // tid within group
    const int wid_g = gtid >> 5;           // warp within group 0..7
    const int lane  = tid & 31;

    float* s_c0  = (float*)(smem + OFF_C0);
    float* s_b1  = (float*)(smem + OFF_B1);
    float* s_ws  = (float*)(smem + OFF_WS);
    float* s_acc = (float*)(smem + OFF_ACC);
    volatile int* s_flag = (volatile int*)(smem + OFF_FLAG);

    unsigned char* xs_ptr = smem + OFF_XS0 + (gid << 15);
    float* s_red = (float*)xs_ptr;          // aliases XS; used post-GEMM1 only
    const uint32_t XS = sb + OFF_XS0 + ((uint32_t)gid << 15);

    // ---- one-time: constants + W0 frags gmem -> SMEM (all 512 threads) ----
    if (tid < 256) s_c0[tid] = g_c0[tid];
    if (tid < 128) { s_b1[tid] = b1[tid]; s_ws[tid] = wsc[tid]; }
    if (tid == 0) { s_acc[0] = 0.f; *s_flag = 0; }
    {
        const float4* s0 = (const float4*)g_W0f;
        float4* d0 = (float4*)(smem + OFF_W0F);
        for (int i = tid; i < 131072 / 16; i += 512) d0[i] = s0[i];
    }
    __syncthreads();

    const float4* feat4 = (const float4*)feat;
    bool first = true;

    for (int tile = blockIdx.x * 2 + gid; tile < NTILES; tile += gridDim.x * 2) {

        // ==== One-time anti-phase stagger: group 1 waits until group 0 has
        // finished its first X DRAM burst. Identical loop periods afterwards
        // keep the groups half-a-pipeline apart (load overlaps GEMMs).
        if (first && gid == 1) {
            while (*s_flag == 0) { }
        }

        // ==== Load X tile: 64 rows x 256 fp32 -> bf16, XOR-swizzled rows ====
        {
            float4 pf[16];
            #pragma unroll
            for (int i = 0; i < 16; i++) {
                int j = i * 256 + gtid;
                int r = j >> 6;
                int cq = j & 63;
                int row_g = tile * TILE_M + r;
                float4 v = make_float4(0.f, 0.f, 0.f, 0.f);
                if (row_g != 0 && row_g < NROWS)
                    v = __ldg(feat4 + (size_t)row_g * 64 + cq);
                pf[i] = v;
            }
            #pragma unroll
            for (int i = 0; i < 16; i++) {
                int j = i * 256 + gtid;
                int r = j >> 6;
                int cq = j & 63;
                uint32_t p0 = pack_bf16(pf[i].x, pf[i].y);
                uint32_t p1 = pack_bf16(pf[i].z, pf[i].w);
                int phys = (cq >> 1) ^ (r & 7);
                uint32_t addr = (uint32_t)(r * 512 + phys * 16 + (cq & 1) * 8);
                *(uint2*)(xs_ptr + addr) = make_uint2(p0, p1);
            }
        }
        if (first && gid == 0 && gtid == 0) {
            __threadfence_block();
            *s_flag = 1;                   // group 0's DRAM burst is done
        }
        first = false;
        GSYNC(gid);

        // ==== GEMM0: D0[64,256] = X[64,256] @ W0f ; warp w -> n [w*32,..) ====
        float acc[4][4][4];
        #pragma unroll
        for (int mt = 0; mt < 4; mt++)
            #pragma unroll
            for (int nt = 0; nt < 4; nt++)
                #pragma unroll
                for (int q = 0; q < 4; q++) acc[mt][nt][q] = 0.f;

        const int r_off = (lane & 7) + ((lane >> 3) & 1) * 8;   // row within m16
        const int u_hi  = (lane >> 4) & 1;                      // +1 unit for k+8

        #pragma unroll
        for (int ks = 0; ks < 16; ks++) {
            uint32_t a[4][4];
            #pragma unroll
            for (int mt = 0; mt < 4; mt++) {
                int r = mt * 16 + r_off;
                int u = ks * 2 + u_hi;
                uint32_t addr = XS + (uint32_t)(r * 512 + (u ^ (r & 7)) * 16);
                LDMATRIX_X4(a[mt][0], a[mt][1], a[mt][2], a[mt][3], addr);
            }
            #pragma unroll
            for (int nt = 0; nt < 4; nt++) {
                int n0 = wid_g * 32 + nt * 8;
                uint2 bv = *(const uint2*)(smem + OFF_W0F
                              + (((n0 >> 3) * 16 + ks) * 256) + lane * 8);
                uint32_t b[2]; b[0] = bv.x; b[1] = bv.y;
                #pragma unroll
                for (int mt = 0; mt < 4; mt++)
                    MMA16816(acc[mt][nt], a[mt], b);
            }
        }
        GSYNC(gid);   // all group warps done reading XS

        // ==== Epilogue0: relu(acc + c0) -> bf16 A-fragments into XS ====
        // accum lane map == A-frag lane map; combine nt pair -> 16B (a0..a3)
        #pragma unroll
        for (int mt = 0; mt < 4; mt++) {
            #pragma unroll
            for (int ntp = 0; ntp < 2; ntp++) {
                int nt0 = ntp * 2, nt1 = nt0 + 1;
                int nA = wid_g * 32 + nt0 * 8 + (lane & 3) * 2;
                int nB = wid_g * 32 + nt1 * 8 + (lane & 3) * 2;
                float cA0 = s_c0[nA], cA1 = s_c0[nA + 1];
                float cB0 = s_c0[nB], cB1 = s_c0[nB + 1];
                uint32_t r0 = pack_bf16(fmaxf(acc[mt][nt0][0] + cA0, 0.f),
                                        fmaxf(acc[mt][nt0][1] + cA1, 0.f));
                uint32_t r1 = pack_bf16(fmaxf(acc[mt][nt0][2] + cA0, 0.f),
                                        fmaxf(acc[mt][nt0][3] + cA1, 0.f));
                uint32_t r2 = pack_bf16(fmaxf(acc[mt][nt1][0] + cB0, 0.f),
                                        fmaxf(acc[mt][nt1][1] + cB1, 0.f));
                uint32_t r3 = pack_bf16(fmaxf(acc[mt][nt1][2] + cB0, 0.f),
                                        fmaxf(acc[mt][nt1][3] + cB1, 0.f));
                int ks1 = wid_g * 2 + ntp;  // this n-range is k-range in GEMM1
                uint32_t off = (uint32_t)((mt * 16 + ks1) * 512 + lane * 16);
                *(uint4*)(xs_ptr + off) = make_uint4(r0, r1, r2, r3);
            }
        }
        GSYNC(gid);

        // ==== GEMM1: D1[64,128] = H0[64,256] @ W1f(global/L2) ; 2(m)x4(n) ====
        const int warp_m = wid_g >> 2;    // 0..1 -> m base warp_m*32
        const int warp_n = wid_g & 3;     // 0..3 -> n base warp_n*32
        float acc2[2][4][4];
        #pragma unroll
        for (int mt = 0; mt < 2; mt++)
            #pragma unroll
            for (int nt = 0; nt < 4; nt++)
                #pragma unroll
                for (int q = 0; q < 4; q++) acc2[mt][nt][q] = 0.f;

        #pragma unroll
        for (int ks = 0; ks < 16; ks++) {
            uint32_t a2[2][4];
            #pragma unroll
            for (int mt = 0; mt < 2; mt++) {
                int mtg = warp_m * 2 + mt;
                uint4 av = *(uint4*)(xs_ptr + (mtg * 16 + ks) * 512 + lane * 16);
                a2[mt][0] = av.x; a2[mt][1] = av.y; a2[mt][2] = av.z; a2[mt][3] = av.w;
            }
            #pragma unroll
            for (int nt = 0; nt < 4; nt++) {
                int n0 = warp_n * 32 + nt * 8;
                uint2 bv = __ldg((const uint2*)(g_W1f
                              + (((n0 >> 3) * 16 + ks) * 256) + lane * 8));
                uint32_t b[2]; b[0] = bv.x; b[1] = bv.y;
                #pragma unroll
                for (int mt = 0; mt < 2; mt++)
                    MMA16816(acc2[mt][nt], a2[mt], b);
            }
        }
        GSYNC(gid);   // done reading XS (H0 frags) -> s_red may alias

        // ==== Epilogue1: score_r = sum_n relu(d + b1[n]) * ws[n] ====
        // Every s_red slot [64 rows][4 warp_n] is written exactly once.
        #pragma unroll
        for (int mt = 0; mt < 2; mt++) {
            float p0 = 0.f, p1 = 0.f;      // rows l/4 and l/4+8 of this m16 tile
            #pragma unroll
            for (int nt = 0; nt < 4; nt++) {
                int n = warp_n * 32 + nt * 8 + (lane & 3) * 2;
                float bb0 = s_b1[n], bb1 = s_b1[n + 1];
                float w0 = s_ws[n],  w1 = s_ws[n + 1];
                p0 = fmaf(fmaxf(acc2[mt][nt][0] + bb0, 0.f), w0, p0);
                p0 = fmaf(fmaxf(acc2[mt][nt][1] + bb1, 0.f), w1, p0);
                p1 = fmaf(fmaxf(acc2[mt][nt][2] + bb0, 0.f), w0, p1);
                p1 = fmaf(fmaxf(acc2[mt][nt][3] + bb1, 0.f), w1, p1);
            }
            p0 += __shfl_xor_sync(0xffffffff, p0, 1);
            p0 += __shfl_xor_sync(0xffffffff, p0, 2);
            p1 += __shfl_xor_sync(0xffffffff, p1, 1);
            p1 += __shfl_xor_sync(0xffffffff, p1, 2);
            if ((lane & 3) == 0) {
                int r = warp_m * 32 + mt * 16 + (lane >> 2);
                s_red[r * 4 + warp_n] = p0;
                s_red[(r + 8) * 4 + warp_n] = p1;
            }
        }
        GSYNC(gid);

        // ==== Fused masked exp + store + CTA partial sum ====
        if (gtid < 64) {      // warps 0-1 of the group (full warps)
            float s = s_red[gtid * 4] + s_red[gtid * 4 + 1]
                    + s_red[gtid * 4 + 2] + s_red[gtid * 4 + 3];
            int row_g = tile * TILE_M + gtid;
            float e = 0.f;
            if (row_g < NOUT) {
                bool m = (row_g < NROWS) ? (adj[row_g] != 0) : true;
                e = m ? expf(s) : 0.f;     // scores are O(0.01): shift-free exp
                g_scores[row_g] = e;
            }
            e += __shfl_xor_sync(0xffffffff, e, 1);
            e += __shfl_xor_sync(0xffffffff, e, 2);
            e += __shfl_xor_sync(0xffffffff, e, 4);
            e += __shfl_xor_sync(0xffffffff, e, 8);
            e += __shfl_xor_sync(0xffffffff, e, 16);
            if (lane == 0) atomicAdd(s_acc, e);
        }
        GSYNC(gid);   // s_red reads done before next tile's X overwrites XS
    }

    __syncthreads();
    if (tid == 0) atomicAdd(&g_total[0], s_acc[0]);
}

// ============================================================================
// Final normalize: out[i] = e_i / sum(e)   (masked entries have e_i = 0)
// ============================================================================
__global__ void finalize(float* __restrict__ out) {
    int i = blockIdx.x * 256 + threadIdx.x;
    if (i < NOUT) out[i] = g_scores[i] / g_total[0];
}

// ============================================================================
// kernel_launch
// ============================================================================
extern "C" void kernel_launch(void* const* d_in, const int* in_sizes, int n_in,
                              void* d_out, int out_size) {
    const int*   adj  = (const int*)d_in[0];
    const float* feat = (const float*)d_in[1];
    const float* W0   = (const float*)d_in[2];
    const float* b0   = (const float*)d_in[3];
    const float* W1   = (const float*)d_in[4];
    const float* b1   = (const float*)d_in[5];
    const float* wsc  = (const float*)d_in[6];
    float* out = (float*)d_out;

    cudaFuncSetAttribute(policy_main,
                         cudaFuncAttributeMaxDynamicSharedMemorySize, SMEM_TOTAL);

    int sms = 148;
    cudaDeviceGetAttribute(&sms, cudaDevAttrMultiProcessorCount, 0);
    if (sms < 1) sms = 148;
    if (sms * 2 > NTILES) sms = (NTILES + 1) / 2;

    prep_all<<<128, 256>>>(W0, W1, feat, b0);
    policy_main<<<sms, 512, SMEM_TOTAL>>>(feat, adj, b1, wsc);
    finalize<<<(NOUT + 255) / 256, 256>>>(out);
}